// round 4
// baseline (speedup 1.0000x reference)
#include <cuda_runtime.h>
#include <cuda_bf16.h>

// ---------------------------------------------------------------------------
// GCNRegression: 2x GCNConv(+relu) + linear head.
// N=100000 nodes, E=1.6M edges, F=128, H=64.
// NOTE: edge_index / batch arrive as int32 (JAX default x64-disabled downcasts
// the reference's jnp.int64 request). Casting them as int64 was the R1 fault.
//
// Pipeline (all on one stream, graph-capturable):
//   1. zero deg, zero aggB
//   2. deg[i]  = sum_{e: dst=i} ew[e]            (scalar atomics)
//   3. dis[i]  = rsqrt(1 + deg[i])
//   4. bufA    = x @ W1^T                        (smem-tiled GEMM)
//   5. aggB   += norm_e * bufA[src_e]  at dst_e  (red.global.add.v4.f32)
//   6. bufB    = relu(aggB + dis^2*bufA + b1)    (in place over aggB)
//   7. bufA    = bufB @ W2^T
//   8. zero bufB
//   9. bufB   += norm_e * bufA[src_e]  at dst_e
//  10. out[i]  = relu(bufB+dis^2*bufA+b2) . W3 + b3   (fused head)
// ---------------------------------------------------------------------------

#define NMAX 100000
#define HID 64

__device__ __align__(16) float g_deg[NMAX];
__device__ __align__(16) float g_dis[NMAX];
__device__ __align__(16) float g_bufA[(size_t)NMAX * HID];
__device__ __align__(16) float g_bufB[(size_t)NMAX * HID];

// ---- zero a float4-aligned buffer -----------------------------------------
__global__ void k_zero4(float4* __restrict__ p, int n4) {
    int i = blockIdx.x * blockDim.x + threadIdx.x;
    if (i < n4) p[i] = make_float4(0.f, 0.f, 0.f, 0.f);
}

// ---- weighted in-degree ----------------------------------------------------
__global__ void k_deg(const int* __restrict__ dst,
                      const float* __restrict__ ew, int E) {
    int e = blockIdx.x * blockDim.x + threadIdx.x;
    if (e < E) atomicAdd(&g_deg[dst[e]], ew[e]);
}

// ---- dis = rsqrt(1 + deg) --------------------------------------------------
__global__ void k_dis(int n) {
    int i = blockIdx.x * blockDim.x + threadIdx.x;
    if (i < n) g_dis[i] = rsqrtf(1.0f + g_deg[i]);
}

// ---- Y[n,64] = X[n,K] @ W[64,K]^T ------------------------------------------
// 256 threads/block = 64 cols x 4 row-slots; each thread does 2 rows.
// W transposed into padded smem: LDS reads Wt[k][c] are conflict-free.
// X row loads are warp-uniform float4 (hardware broadcast, L1-friendly).
template <int K>
__global__ void k_gemm(const float* __restrict__ X, const float* __restrict__ W,
                       float* __restrict__ Y, int n) {
    __shared__ float Wt[K][HID + 1];
    for (int idx = threadIdx.x; idx < K * HID; idx += blockDim.x) {
        int h = idx / K;
        int k = idx - h * K;
        Wt[k][h] = W[idx];
    }
    __syncthreads();

    const int c  = threadIdx.x & 63;
    const int rs = threadIdx.x >> 6;                  // 0..3
    const long long i0 = (long long)blockIdx.x * 8 + rs;
    const long long i1 = i0 + 4;
    const bool v0 = i0 < n, v1 = i1 < n;

    const float4* x0 = (const float4*)(X + i0 * K);
    const float4* x1 = (const float4*)(X + i1 * K);

    float acc0 = 0.f, acc1 = 0.f;
#pragma unroll
    for (int k = 0; k < K; k += 4) {
        float4 a0 = v0 ? x0[k >> 2] : make_float4(0.f, 0.f, 0.f, 0.f);
        float4 a1 = v1 ? x1[k >> 2] : make_float4(0.f, 0.f, 0.f, 0.f);
        float w0 = Wt[k + 0][c];
        float w1 = Wt[k + 1][c];
        float w2 = Wt[k + 2][c];
        float w3 = Wt[k + 3][c];
        acc0 = fmaf(a0.x, w0, fmaf(a0.y, w1, fmaf(a0.z, w2, fmaf(a0.w, w3, acc0))));
        acc1 = fmaf(a1.x, w0, fmaf(a1.y, w1, fmaf(a1.z, w2, fmaf(a1.w, w3, acc1))));
    }
    if (v0) Y[i0 * HID + c] = acc0;
    if (v1) Y[i1 * HID + c] = acc1;
}

// ---- edge aggregation: half-warp (16 lanes) per edge -----------------------
// agg[dst] += dis[src]*ew*dis[dst] * xw[src]  via red.global.add.v4.f32
__global__ void k_edge(const int* __restrict__ src,
                       const int* __restrict__ dst,
                       const float* __restrict__ ew,
                       const float* __restrict__ xw,
                       float* __restrict__ agg, int E) {
    long long gid = (long long)blockIdx.x * blockDim.x + threadIdx.x;
    int  lane = (int)(gid & 15);
    long long e = gid >> 4;
    if (e >= E) return;

    int s = src[e];
    int d = dst[e];
    float coef = g_dis[s] * ew[e] * g_dis[d];

    float4 v = ((const float4*)(xw + (long long)s * HID))[lane];
    float* p = agg + (long long)d * HID + (long long)lane * 4;
    asm volatile("red.global.add.v4.f32 [%0], {%1,%2,%3,%4};"
                 :: "l"(p), "f"(coef * v.x), "f"(coef * v.y),
                    "f"(coef * v.z), "f"(coef * v.w)
                 : "memory");
}

// ---- epilogue layer: agg = relu(agg + dis^2*xw + b) (in place, float4) -----
__global__ void k_epi(float* __restrict__ agg, const float* __restrict__ xw,
                      const float* __restrict__ b, int n) {
    long long idx = (long long)blockIdx.x * blockDim.x + threadIdx.x;
    if (idx >= (long long)n * 16) return;
    int i  = (int)(idx >> 4);
    int c4 = (int)(idx & 15);
    float ds = g_dis[i];
    float d2 = ds * ds;
    float4 a  = ((float4*)agg)[idx];
    float4 v  = ((const float4*)xw)[idx];
    float4 bb = ((const float4*)b)[c4];
    a.x = fmaxf(fmaf(d2, v.x, a.x) + bb.x, 0.f);
    a.y = fmaxf(fmaf(d2, v.y, a.y) + bb.y, 0.f);
    a.z = fmaxf(fmaf(d2, v.z, a.z) + bb.z, 0.f);
    a.w = fmaxf(fmaf(d2, v.w, a.w) + bb.w, 0.f);
    ((float4*)agg)[idx] = a;
}

// ---- fused final epilogue + head: out = relu(agg+dis^2*xw+b2) . W3 + b3 ----
__global__ void k_head(const float* __restrict__ agg, const float* __restrict__ xw,
                       const float* __restrict__ b2, const float* __restrict__ W3,
                       const float* __restrict__ b3, float* __restrict__ out, int n) {
    int warp = (blockIdx.x * blockDim.x + threadIdx.x) >> 5;
    int lane = threadIdx.x & 31;
    if (warp >= n) return;
    float ds = g_dis[warp];
    float d2 = ds * ds;
    const float* ap = agg + (long long)warp * HID;
    const float* vp = xw  + (long long)warp * HID;
    float sum = 0.f;
#pragma unroll
    for (int t = 0; t < 2; t++) {
        int c = lane + t * 32;
        float h = fmaxf(fmaf(d2, vp[c], ap[c]) + b2[c], 0.f);
        sum = fmaf(h, W3[c], sum);
    }
#pragma unroll
    for (int off = 16; off; off >>= 1)
        sum += __shfl_xor_sync(0xffffffffu, sum, off);
    if (lane == 0) out[warp] = sum + b3[0];
}

extern "C" void kernel_launch(void* const* d_in, const int* in_sizes, int n_in,
                              void* d_out, int out_size) {
    const float* x   = (const float*)d_in[0];
    const int*   ei  = (const int*)d_in[1];       // int32! (JAX x64 disabled)
    const float* ew  = (const float*)d_in[2];
    // d_in[3] = batch (int32, unused)
    const float* W1  = (const float*)d_in[4];
    const float* b1  = (const float*)d_in[5];
    const float* W2  = (const float*)d_in[6];
    const float* b2  = (const float*)d_in[7];
    const float* W3  = (const float*)d_in[8];
    const float* b3  = (const float*)d_in[9];
    float*       out = (float*)d_out;

    const int n = in_sizes[0] / 128;   // 100000
    const int E = in_sizes[1] / 2;     // 1600000
    const int* src = ei;
    const int* dst = ei + E;

    float *dDeg, *dDis, *dA, *dB;
    cudaGetSymbolAddress((void**)&dDeg, g_deg);
    cudaGetSymbolAddress((void**)&dDis, g_dis);
    cudaGetSymbolAddress((void**)&dA,   g_bufA);
    cudaGetSymbolAddress((void**)&dB,   g_bufB);
    (void)dDis;

    const int TB = 256;
    const int nh4 = n * 16;                       // n*64/4 float4s
    const long long edgeThreads = (long long)E * 16;

    // 1. zero deg + aggB
    k_zero4<<<((n + 3) / 4 + TB - 1) / TB, TB>>>((float4*)dDeg, (n + 3) / 4);
    k_zero4<<<(nh4 + TB - 1) / TB, TB>>>((float4*)dB, nh4);
    // 2-3. degree + rsqrt
    k_deg<<<(E + TB - 1) / TB, TB>>>(dst, ew, E);
    k_dis<<<(n + TB - 1) / TB, TB>>>(n);
    // 4. xw1 = x @ W1^T
    k_gemm<128><<<(n + 7) / 8, TB>>>(x, W1, dA, n);
    // 5. scatter layer 1
    k_edge<<<(int)((edgeThreads + TB - 1) / TB), TB>>>(src, dst, ew, dA, dB, E);
    // 6. h1 = relu(...)  (in place over bufB)
    k_epi<<<(nh4 + TB - 1) / TB, TB>>>(dB, dA, b1, n);
    // 7. xw2 = h1 @ W2^T
    k_gemm<64><<<(n + 7) / 8, TB>>>(dB, W2, dA, n);
    // 8. zero aggB
    k_zero4<<<(nh4 + TB - 1) / TB, TB>>>((float4*)dB, nh4);
    // 9. scatter layer 2
    k_edge<<<(int)((edgeThreads + TB - 1) / TB), TB>>>(src, dst, ew, dA, dB, E);
    // 10. fused relu + head
    k_head<<<(n * 32 + TB - 1) / TB, TB>>>(dB, dA, b2, W3, b3, out, n);
}

// round 5
// speedup vs baseline: 1.4586x; 1.4586x over previous
#include <cuda_runtime.h>
#include <cuda_bf16.h>

// ---------------------------------------------------------------------------
// GCNRegression: 2x GCNConv(+relu) + linear head.
// N=100000 nodes, E=1.6M edges, F=128, H=64. edge_index arrives int32.
//
// R5: CSR build (hist + scan + scatter) replaces atomic scatter-add.
// Aggregation = 1 warp/node segmented reduction, epilogue+head fused in.
//
//   1. zero deg/cnt
//   2. deg[d]+=ew, cnt[d]++                  (per edge)
//   3. dis = rsqrt(1+deg)
//   4. rowptr = exclusive_scan(cnt)          (3 small kernels)
//   5. scatter: esrc/ecoef in dst-sorted order
//   6. bufA = x @ W1^T
//   7. bufB[i] = relu(sum_seg coef*bufA[src] + dis_i^2*bufA[i] + b1)
//   8. bufA = bufB @ W2^T
//   9. out[i] = relu(sum_seg ... + b2) . W3 + b3
// ---------------------------------------------------------------------------

#define NMAX 100000
#define EMAX 1600000
#define HID 64
#define SCAN_CHUNK 4096

__device__ __align__(16) float g_deg[NMAX];
__device__ __align__(16) float g_dis[NMAX];
__device__ __align__(16) int   g_cnt[NMAX];
__device__ __align__(16) int   g_rowptr[NMAX + 1];
__device__ __align__(16) int   g_pos[NMAX];
__device__ __align__(16) int   g_bsum[1024];
__device__ __align__(16) int   g_boff[1024];
__device__ __align__(16) int   g_esrc[EMAX];
__device__ __align__(16) float g_ecoef[EMAX];
__device__ __align__(16) float g_bufA[(size_t)NMAX * HID];
__device__ __align__(16) float g_bufB[(size_t)NMAX * HID];

// ---- zero deg + cnt --------------------------------------------------------
__global__ void k_zero_di(int n) {
    int i = blockIdx.x * blockDim.x + threadIdx.x;
    if (i < n) { g_deg[i] = 0.f; g_cnt[i] = 0; }
}

// ---- weighted in-degree + histogram ---------------------------------------
__global__ void k_deg_hist(const int* __restrict__ dst,
                           const float* __restrict__ ew, int E) {
    int e = blockIdx.x * blockDim.x + threadIdx.x;
    if (e < E) {
        int d = dst[e];
        atomicAdd(&g_deg[d], ew[e]);
        atomicAdd(&g_cnt[d], 1);
    }
}

// ---- dis = rsqrt(1 + deg) --------------------------------------------------
__global__ void k_dis(int n) {
    int i = blockIdx.x * blockDim.x + threadIdx.x;
    if (i < n) g_dis[i] = rsqrtf(1.0f + g_deg[i]);
}

// ---- scan phase 1: per-block (4096-chunk) exclusive scan of cnt ------------
__global__ void k_scan1(int n) {
    __shared__ int ts[1024];
    int t = threadIdx.x, b = blockIdx.x;
    int base = b * SCAN_CHUNK + t * 4;
    int c0 = (base + 0 < n) ? g_cnt[base + 0] : 0;
    int c1 = (base + 1 < n) ? g_cnt[base + 1] : 0;
    int c2 = (base + 2 < n) ? g_cnt[base + 2] : 0;
    int c3 = (base + 3 < n) ? g_cnt[base + 3] : 0;
    int s = c0 + c1 + c2 + c3;
    ts[t] = s;
    __syncthreads();
    for (int d = 1; d < 1024; d <<= 1) {
        int v = (t >= d) ? ts[t - d] : 0;
        __syncthreads();
        ts[t] += v;
        __syncthreads();
    }
    int excl = ts[t] - s;
    if (base + 0 < n) g_rowptr[base + 0] = excl;
    if (base + 1 < n) g_rowptr[base + 1] = excl + c0;
    if (base + 2 < n) g_rowptr[base + 2] = excl + c0 + c1;
    if (base + 3 < n) g_rowptr[base + 3] = excl + c0 + c1 + c2;
    if (t == 1023) g_bsum[b] = ts[1023];
}

// ---- scan phase 2: scan block sums (nb <= 1024) ----------------------------
__global__ void k_scan2(int nb, int n, int E) {
    __shared__ int ts[1024];
    int t = threadIdx.x;
    int v = (t < nb) ? g_bsum[t] : 0;
    ts[t] = v;
    __syncthreads();
    for (int d = 1; d < 1024; d <<= 1) {
        int u = (t >= d) ? ts[t - d] : 0;
        __syncthreads();
        ts[t] += u;
        __syncthreads();
    }
    if (t < nb) g_boff[t] = ts[t] - v;
    if (t == 0) g_rowptr[n] = E;
}

// ---- scan phase 3: add block offsets, init cursors -------------------------
__global__ void k_scan3(int n) {
    int i = blockIdx.x * blockDim.x + threadIdx.x;
    if (i < n) {
        int r = g_rowptr[i] + g_boff[i / SCAN_CHUNK];
        g_rowptr[i] = r;
        g_pos[i] = r;
    }
}

// ---- scatter edges into dst-sorted CSR order -------------------------------
__global__ void k_scatter(const int* __restrict__ src,
                          const int* __restrict__ dst,
                          const float* __restrict__ ew, int E) {
    int e = blockIdx.x * blockDim.x + threadIdx.x;
    if (e >= E) return;
    int s = src[e];
    int d = dst[e];
    int p = atomicAdd(&g_pos[d], 1);
    g_esrc[p] = s;
    g_ecoef[p] = g_dis[s] * ew[e] * g_dis[d];
}

// ---- Y[n,64] = X[n,K] @ W[64,K]^T ; 4 rows/thread --------------------------
template <int K>
__global__ void k_gemm(const float* __restrict__ X, const float* __restrict__ W,
                       float* __restrict__ Y, int n) {
    __shared__ float Wt[K][HID + 1];
    for (int idx = threadIdx.x; idx < K * HID; idx += blockDim.x) {
        int h = idx / K;
        int k = idx - h * K;
        Wt[k][h] = W[idx];
    }
    __syncthreads();

    const int c  = threadIdx.x & 63;
    const int rs = threadIdx.x >> 6;                // 0..3
    const long long row0 = (long long)blockIdx.x * 16 + rs * 4;

    bool v[4];
    const float4* xp[4];
#pragma unroll
    for (int r = 0; r < 4; r++) {
        v[r]  = (row0 + r) < n;
        xp[r] = (const float4*)(X + (row0 + r) * K);
    }
    float acc[4] = {0.f, 0.f, 0.f, 0.f};
#pragma unroll
    for (int k = 0; k < K; k += 4) {
        float w0 = Wt[k + 0][c];
        float w1 = Wt[k + 1][c];
        float w2 = Wt[k + 2][c];
        float w3 = Wt[k + 3][c];
#pragma unroll
        for (int r = 0; r < 4; r++) {
            float4 a = v[r] ? xp[r][k >> 2] : make_float4(0.f, 0.f, 0.f, 0.f);
            acc[r] = fmaf(a.x, w0, fmaf(a.y, w1, fmaf(a.z, w2, fmaf(a.w, w3, acc[r]))));
        }
    }
#pragma unroll
    for (int r = 0; r < 4; r++)
        if (v[r]) Y[(row0 + r) * HID + c] = acc[r];
}

// ---- segmented-sum body: acc (float2/lane) over a node's edge list ---------
__device__ __forceinline__ void agg_body(const float* __restrict__ xw,
                                         int node, int lane,
                                         float& ax, float& ay) {
    int j   = g_rowptr[node];
    int end = g_rowptr[node + 1];
    for (; j + 3 < end; j += 4) {
        int   s0 = g_esrc[j],     s1 = g_esrc[j + 1];
        int   s2 = g_esrc[j + 2], s3 = g_esrc[j + 3];
        float c0 = g_ecoef[j],     c1 = g_ecoef[j + 1];
        float c2 = g_ecoef[j + 2], c3 = g_ecoef[j + 3];
        float2 v0 = __ldg((const float2*)(xw + (size_t)s0 * HID) + lane);
        float2 v1 = __ldg((const float2*)(xw + (size_t)s1 * HID) + lane);
        float2 v2 = __ldg((const float2*)(xw + (size_t)s2 * HID) + lane);
        float2 v3 = __ldg((const float2*)(xw + (size_t)s3 * HID) + lane);
        ax = fmaf(c0, v0.x, ax); ay = fmaf(c0, v0.y, ay);
        ax = fmaf(c1, v1.x, ax); ay = fmaf(c1, v1.y, ay);
        ax = fmaf(c2, v2.x, ax); ay = fmaf(c2, v2.y, ay);
        ax = fmaf(c3, v3.x, ax); ay = fmaf(c3, v3.y, ay);
    }
    for (; j < end; j++) {
        int   s = g_esrc[j];
        float cc = g_ecoef[j];
        float2 v = __ldg((const float2*)(xw + (size_t)s * HID) + lane);
        ax = fmaf(cc, v.x, ax); ay = fmaf(cc, v.y, ay);
    }
}

// ---- layer aggregation + self-loop + bias + relu (1 warp/node) -------------
__global__ void k_agg_relu(const float* __restrict__ xw,
                           const float* __restrict__ b,
                           float* __restrict__ out, int n) {
    int node = (blockIdx.x * blockDim.x + threadIdx.x) >> 5;
    int lane = threadIdx.x & 31;
    if (node >= n) return;
    float ax = 0.f, ay = 0.f;
    agg_body(xw, node, lane, ax, ay);
    float ds = g_dis[node];
    float d2 = ds * ds;
    float2 xv = __ldg((const float2*)(xw + (size_t)node * HID) + lane);
    float2 bb = __ldg((const float2*)b + lane);
    float2 r;
    r.x = fmaxf(fmaf(d2, xv.x, ax) + bb.x, 0.f);
    r.y = fmaxf(fmaf(d2, xv.y, ay) + bb.y, 0.f);
    ((float2*)(out + (size_t)node * HID))[lane] = r;
}

// ---- final aggregation + relu + head dot W3 (1 warp/node) ------------------
__global__ void k_agg_head(const float* __restrict__ xw,
                           const float* __restrict__ b2,
                           const float* __restrict__ W3,
                           const float* __restrict__ b3,
                           float* __restrict__ out, int n) {
    int node = (blockIdx.x * blockDim.x + threadIdx.x) >> 5;
    int lane = threadIdx.x & 31;
    if (node >= n) return;
    float ax = 0.f, ay = 0.f;
    agg_body(xw, node, lane, ax, ay);
    float ds = g_dis[node];
    float d2 = ds * ds;
    float2 xv = __ldg((const float2*)(xw + (size_t)node * HID) + lane);
    float2 bb = __ldg((const float2*)b2 + lane);
    float h0 = fmaxf(fmaf(d2, xv.x, ax) + bb.x, 0.f);
    float h1 = fmaxf(fmaf(d2, xv.y, ay) + bb.y, 0.f);
    float2 w = __ldg((const float2*)W3 + lane);
    float sum = fmaf(h0, w.x, h1 * w.y);
#pragma unroll
    for (int off = 16; off; off >>= 1)
        sum += __shfl_xor_sync(0xffffffffu, sum, off);
    if (lane == 0) out[node] = sum + b3[0];
}

extern "C" void kernel_launch(void* const* d_in, const int* in_sizes, int n_in,
                              void* d_out, int out_size) {
    const float* x   = (const float*)d_in[0];
    const int*   ei  = (const int*)d_in[1];       // int32 (JAX x64 disabled)
    const float* ew  = (const float*)d_in[2];
    // d_in[3] = batch (unused)
    const float* W1  = (const float*)d_in[4];
    const float* b1  = (const float*)d_in[5];
    const float* W2  = (const float*)d_in[6];
    const float* b2  = (const float*)d_in[7];
    const float* W3  = (const float*)d_in[8];
    const float* b3  = (const float*)d_in[9];
    float*       out = (float*)d_out;

    const int n = in_sizes[0] / 128;   // 100000
    const int E = in_sizes[1] / 2;     // 1600000
    const int* src = ei;
    const int* dst = ei + E;

    float *dA, *dB;
    cudaGetSymbolAddress((void**)&dA, g_bufA);
    cudaGetSymbolAddress((void**)&dB, g_bufB);

    const int TB = 256;
    const int NB = (n + SCAN_CHUNK - 1) / SCAN_CHUNK;

    // CSR build (reused by both layers)
    k_zero_di<<<(n + TB - 1) / TB, TB>>>(n);
    k_deg_hist<<<(E + TB - 1) / TB, TB>>>(dst, ew, E);
    k_dis<<<(n + TB - 1) / TB, TB>>>(n);
    k_scan1<<<NB, 1024>>>(n);
    k_scan2<<<1, 1024>>>(NB, n, E);
    k_scan3<<<(n + TB - 1) / TB, TB>>>(n);
    k_scatter<<<(E + TB - 1) / TB, TB>>>(src, dst, ew, E);

    // layer 1
    k_gemm<128><<<(n + 15) / 16, TB>>>(x, W1, dA, n);
    k_agg_relu<<<(n * 32 + TB - 1) / TB, TB>>>(dA, b1, dB, n);
    // layer 2 + head
    k_gemm<64><<<(n + 15) / 16, TB>>>(dB, W2, dA, n);
    k_agg_head<<<(n * 32 + TB - 1) / TB, TB>>>(dA, b2, W3, b3, out, n);
}

// round 6
// speedup vs baseline: 1.4601x; 1.0010x over previous
#include <cuda_runtime.h>
#include <cuda_bf16.h>

// ---------------------------------------------------------------------------
// GCNRegression: 2x GCNConv(+relu) + linear head.
// N=100000, E=1.6M, F=128, H=64. edge_index arrives int32.
//
// R6: (a) CSR build chain runs on a second stream, overlapped with gemm128
//     via event fork/join (graph-capturable pattern);
//     (b) GEMMs use packed fma.rn.f32x2 (2 FMA/inst, paired along K);
//     (c) edge meta packed to one float2 {src_bits, coef};
//     (d) dis fused into scan1.
// ---------------------------------------------------------------------------

#define NMAX 100000
#define EMAX 1600000
#define HID 64
#define SCAN_CHUNK 4096

__device__ __align__(16) float  g_deg[NMAX];
__device__ __align__(16) float  g_dis[NMAX];
__device__ __align__(16) int    g_cnt[NMAX];
__device__ __align__(16) int    g_rowptr[NMAX + 1];
__device__ __align__(16) int    g_pos[NMAX];
__device__ __align__(16) int    g_bsum[1024];
__device__ __align__(16) int    g_boff[1024];
__device__ __align__(16) float2 g_edge[EMAX];          // {src_as_float_bits, coef}
__device__ __align__(16) float  g_bufA[(size_t)NMAX * HID];
__device__ __align__(16) float  g_bufB[(size_t)NMAX * HID];

typedef unsigned long long ull;

// packed dual fp32 FMA: acc = a*w + acc (elementwise on 2-wide packs)
__device__ __forceinline__ void ffma2(ull& acc, ull a, ull w) {
    asm("fma.rn.f32x2 %0, %1, %2, %0;" : "+l"(acc) : "l"(a), "l"(w));
}
__device__ __forceinline__ float hsum2(ull v) {
    float2 f = *reinterpret_cast<float2*>(&v);
    return f.x + f.y;
}

// ---- zero deg + cnt --------------------------------------------------------
__global__ void k_zero_di(int n) {
    int i = blockIdx.x * blockDim.x + threadIdx.x;
    if (i < n) { g_deg[i] = 0.f; g_cnt[i] = 0; }
}

// ---- weighted in-degree + histogram ---------------------------------------
__global__ void k_deg_hist(const int* __restrict__ dst,
                           const float* __restrict__ ew, int E) {
    int e = blockIdx.x * blockDim.x + threadIdx.x;
    if (e < E) {
        int d = dst[e];
        atomicAdd(&g_deg[d], ew[e]);
        atomicAdd(&g_cnt[d], 1);
    }
}

// ---- scan phase 1 (+ fused dis = rsqrt(1+deg)) -----------------------------
__global__ void k_scan1(int n) {
    __shared__ int ts[1024];
    int t = threadIdx.x, b = blockIdx.x;
    int base = b * SCAN_CHUNK + t * 4;
    int c0 = (base + 0 < n) ? g_cnt[base + 0] : 0;
    int c1 = (base + 1 < n) ? g_cnt[base + 1] : 0;
    int c2 = (base + 2 < n) ? g_cnt[base + 2] : 0;
    int c3 = (base + 3 < n) ? g_cnt[base + 3] : 0;
#pragma unroll
    for (int r = 0; r < 4; r++)
        if (base + r < n) g_dis[base + r] = rsqrtf(1.0f + g_deg[base + r]);
    int s = c0 + c1 + c2 + c3;
    ts[t] = s;
    __syncthreads();
    for (int d = 1; d < 1024; d <<= 1) {
        int v = (t >= d) ? ts[t - d] : 0;
        __syncthreads();
        ts[t] += v;
        __syncthreads();
    }
    int excl = ts[t] - s;
    if (base + 0 < n) g_rowptr[base + 0] = excl;
    if (base + 1 < n) g_rowptr[base + 1] = excl + c0;
    if (base + 2 < n) g_rowptr[base + 2] = excl + c0 + c1;
    if (base + 3 < n) g_rowptr[base + 3] = excl + c0 + c1 + c2;
    if (t == 1023) g_bsum[b] = ts[1023];
}

// ---- scan phase 2: scan block sums (nb <= 1024) ----------------------------
__global__ void k_scan2(int nb, int n, int E) {
    __shared__ int ts[1024];
    int t = threadIdx.x;
    int v = (t < nb) ? g_bsum[t] : 0;
    ts[t] = v;
    __syncthreads();
    for (int d = 1; d < 1024; d <<= 1) {
        int u = (t >= d) ? ts[t - d] : 0;
        __syncthreads();
        ts[t] += u;
        __syncthreads();
    }
    if (t < nb) g_boff[t] = ts[t] - v;
    if (t == 0) g_rowptr[n] = E;
}

// ---- scan phase 3: add block offsets, init cursors -------------------------
__global__ void k_scan3(int n) {
    int i = blockIdx.x * blockDim.x + threadIdx.x;
    if (i < n) {
        int r = g_rowptr[i] + g_boff[i / SCAN_CHUNK];
        g_rowptr[i] = r;
        g_pos[i] = r;
    }
}

// ---- scatter edges into dst-sorted CSR order (packed meta) -----------------
__global__ void k_scatter(const int* __restrict__ src,
                          const int* __restrict__ dst,
                          const float* __restrict__ ew, int E) {
    int e = blockIdx.x * blockDim.x + threadIdx.x;
    if (e >= E) return;
    int s = src[e];
    int d = dst[e];
    int p = atomicAdd(&g_pos[d], 1);
    g_edge[p] = make_float2(__int_as_float(s), g_dis[s] * ew[e] * g_dis[d]);
}

// ---- Y[n,64] = X[n,K] @ W[64,K]^T ; packed-f32x2 along K -------------------
// 256 thr = 64 cols x 4 row-slots, 4 rows/thread. W staged in smem as
// k-pair float2 (Wp[kk][c] = {W[c][2kk], W[c][2kk+1]}), x loaded as
// ulonglong2 (two packed f32 pairs per float4). acc keeps even/odd-k
// partial sums packed; horizontal add at the end.
template <int K>
__global__ void k_gemm(const float* __restrict__ X, const float* __restrict__ W,
                       float* __restrict__ Y, int n) {
    __shared__ float2 Wp[K / 2][HID + 1];
    const float2* Wf2 = (const float2*)W;
    for (int idx = threadIdx.x; idx < HID * (K / 2); idx += blockDim.x) {
        int c  = idx / (K / 2);
        int kk = idx - c * (K / 2);
        Wp[kk][c] = Wf2[c * (K / 2) + kk];
    }
    __syncthreads();

    const int c  = threadIdx.x & 63;
    const int rs = threadIdx.x >> 6;                // 0..3
    const long long row0 = (long long)blockIdx.x * 16 + rs * 4;

    bool v[4];
    const ulonglong2* xq[4];
#pragma unroll
    for (int r = 0; r < 4; r++) {
        v[r]  = (row0 + r) < n;
        xq[r] = (const ulonglong2*)(X + (row0 + r) * K);
    }
    ull acc[4] = {0ull, 0ull, 0ull, 0ull};
#pragma unroll
    for (int kk = 0; kk < K / 2; kk += 2) {
        ull w0 = *reinterpret_cast<const ull*>(&Wp[kk + 0][c]);
        ull w1 = *reinterpret_cast<const ull*>(&Wp[kk + 1][c]);
#pragma unroll
        for (int r = 0; r < 4; r++) {
            ulonglong2 a = v[r] ? xq[r][kk >> 1] : make_ulonglong2(0ull, 0ull);
            ffma2(acc[r], a.x, w0);
            ffma2(acc[r], a.y, w1);
        }
    }
#pragma unroll
    for (int r = 0; r < 4; r++)
        if (v[r]) Y[(row0 + r) * HID + c] = hsum2(acc[r]);
}

// ---- segmented-sum body: acc (float2/lane) over a node's edge list ---------
__device__ __forceinline__ void agg_body(const float* __restrict__ xw,
                                         int node, int lane,
                                         float& ax, float& ay) {
    int j   = g_rowptr[node];
    int end = g_rowptr[node + 1];
    for (; j + 3 < end; j += 4) {
        float2 m0 = g_edge[j],     m1 = g_edge[j + 1];
        float2 m2 = g_edge[j + 2], m3 = g_edge[j + 3];
        int s0 = __float_as_int(m0.x), s1 = __float_as_int(m1.x);
        int s2 = __float_as_int(m2.x), s3 = __float_as_int(m3.x);
        float2 v0 = __ldg((const float2*)(xw + (size_t)s0 * HID) + lane);
        float2 v1 = __ldg((const float2*)(xw + (size_t)s1 * HID) + lane);
        float2 v2 = __ldg((const float2*)(xw + (size_t)s2 * HID) + lane);
        float2 v3 = __ldg((const float2*)(xw + (size_t)s3 * HID) + lane);
        ax = fmaf(m0.y, v0.x, ax); ay = fmaf(m0.y, v0.y, ay);
        ax = fmaf(m1.y, v1.x, ax); ay = fmaf(m1.y, v1.y, ay);
        ax = fmaf(m2.y, v2.x, ax); ay = fmaf(m2.y, v2.y, ay);
        ax = fmaf(m3.y, v3.x, ax); ay = fmaf(m3.y, v3.y, ay);
    }
    for (; j < end; j++) {
        float2 m = g_edge[j];
        int s = __float_as_int(m.x);
        float2 v = __ldg((const float2*)(xw + (size_t)s * HID) + lane);
        ax = fmaf(m.y, v.x, ax); ay = fmaf(m.y, v.y, ay);
    }
}

// ---- layer aggregation + self-loop + bias + relu (1 warp/node) -------------
__global__ void k_agg_relu(const float* __restrict__ xw,
                           const float* __restrict__ b,
                           float* __restrict__ out, int n) {
    int node = (blockIdx.x * blockDim.x + threadIdx.x) >> 5;
    int lane = threadIdx.x & 31;
    if (node >= n) return;
    float ax = 0.f, ay = 0.f;
    agg_body(xw, node, lane, ax, ay);
    float ds = g_dis[node];
    float d2 = ds * ds;
    float2 xv = __ldg((const float2*)(xw + (size_t)node * HID) + lane);
    float2 bb = __ldg((const float2*)b + lane);
    float2 r;
    r.x = fmaxf(fmaf(d2, xv.x, ax) + bb.x, 0.f);
    r.y = fmaxf(fmaf(d2, xv.y, ay) + bb.y, 0.f);
    ((float2*)(out + (size_t)node * HID))[lane] = r;
}

// ---- final aggregation + relu + head dot W3 (1 warp/node) ------------------
__global__ void k_agg_head(const float* __restrict__ xw,
                           const float* __restrict__ b2,
                           const float* __restrict__ W3,
                           const float* __restrict__ b3,
                           float* __restrict__ out, int n) {
    int node = (blockIdx.x * blockDim.x + threadIdx.x) >> 5;
    int lane = threadIdx.x & 31;
    if (node >= n) return;
    float ax = 0.f, ay = 0.f;
    agg_body(xw, node, lane, ax, ay);
    float ds = g_dis[node];
    float d2 = ds * ds;
    float2 xv = __ldg((const float2*)(xw + (size_t)node * HID) + lane);
    float2 bb = __ldg((const float2*)b2 + lane);
    float h0 = fmaxf(fmaf(d2, xv.x, ax) + bb.x, 0.f);
    float h1 = fmaxf(fmaf(d2, xv.y, ay) + bb.y, 0.f);
    float2 w = __ldg((const float2*)W3 + lane);
    float sum = fmaf(h0, w.x, h1 * w.y);
#pragma unroll
    for (int off = 16; off; off >>= 1)
        sum += __shfl_xor_sync(0xffffffffu, sum, off);
    if (lane == 0) out[node] = sum + b3[0];
}

extern "C" void kernel_launch(void* const* d_in, const int* in_sizes, int n_in,
                              void* d_out, int out_size) {
    const float* x   = (const float*)d_in[0];
    const int*   ei  = (const int*)d_in[1];       // int32 (JAX x64 disabled)
    const float* ew  = (const float*)d_in[2];
    // d_in[3] = batch (unused)
    const float* W1  = (const float*)d_in[4];
    const float* b1  = (const float*)d_in[5];
    const float* W2  = (const float*)d_in[6];
    const float* b2  = (const float*)d_in[7];
    const float* W3  = (const float*)d_in[8];
    const float* b3  = (const float*)d_in[9];
    float*       out = (float*)d_out;

    const int n = in_sizes[0] / 128;   // 100000
    const int E = in_sizes[1] / 2;     // 1600000
    const int* src = ei;
    const int* dst = ei + E;

    float *dA, *dB;
    cudaGetSymbolAddress((void**)&dA, g_bufA);
    cudaGetSymbolAddress((void**)&dB, g_bufB);

    const int TB = 256;
    const int NB = (n + SCAN_CHUNK - 1) / SCAN_CHUNK;

    // fork: CSR build chain on s2, overlapped with gemm128 on stream 0.
    // (stream/events intentionally not destroyed: they are referenced by the
    // captured graph; kernel_launch is invoked only twice by the harness)
    cudaStream_t s2;
    cudaEvent_t evA, evB;
    cudaStreamCreateWithFlags(&s2, cudaStreamNonBlocking);
    cudaEventCreateWithFlags(&evA, cudaEventDisableTiming);
    cudaEventCreateWithFlags(&evB, cudaEventDisableTiming);

    cudaEventRecord(evA, 0);
    cudaStreamWaitEvent(s2, evA, 0);

    // -- CSR chain (s2)
    k_zero_di<<<(n + TB - 1) / TB, TB, 0, s2>>>(n);
    k_deg_hist<<<(E + TB - 1) / TB, TB, 0, s2>>>(dst, ew, E);
    k_scan1<<<NB, 1024, 0, s2>>>(n);
    k_scan2<<<1, 1024, 0, s2>>>(NB, n, E);
    k_scan3<<<(n + TB - 1) / TB, TB, 0, s2>>>(n);
    k_scatter<<<(E + TB - 1) / TB, TB, 0, s2>>>(src, dst, ew, E);
    cudaEventRecord(evB, s2);

    // -- stream 0: xw1 = x @ W1^T (independent of CSR chain)
    k_gemm<128><<<(n + 15) / 16, TB>>>(x, W1, dA, n);

    // join, then serial tail
    cudaStreamWaitEvent(0, evB, 0);
    k_agg_relu<<<(n * 32 + TB - 1) / TB, TB>>>(dA, b1, dB, n);
    k_gemm<64><<<(n + 15) / 16, TB>>>(dB, W2, dA, n);
    k_agg_head<<<(n * 32 + TB - 1) / TB, TB>>>(dA, b2, W3, b3, out, n);
}